// round 9
// baseline (speedup 1.0000x reference)
#include <cuda_runtime.h>

#define NN 50000
#define EE 800000
#define FF 128
#define HH 64
#define CC 40

typedef unsigned long long u64;

// ---------------- scratch (device globals: no allocation allowed) ----------
__device__ __align__(16) float g_y1[NN * HH];    // x @ Wl1
__device__ __align__(16) float g_z1[NN * HH];    // x @ Wr1
__device__ __align__(16) float g_xa[NN * HH];    // x @ Wlin[0:128]
__device__ __align__(16) float g_hid[NN * HH];   // relu(l2norm(mean + bl1 + z1))
__device__ __align__(16) float g_h[NN * HH];     // relu(xa + hid @ Wlin[128:] + blin)
__device__ __align__(16) float g_y2[NN * CC];    // h @ Wl2
__device__ __align__(16) float g_z2[NN * CC];    // h @ Wr2
__device__ int g_cnt[NN];                        // in-degree
__device__ int g_rowp[NN + 1];                   // CSR row pointers (by dst)
__device__ int g_cur[NN];                        // fill cursors
__device__ int g_adj[EE];                        // CSR: src indices grouped by dst
__device__ int g_src[EE];                        // normalized int32 src
__device__ int g_dst[EE];                        // normalized int32 dst
__device__ int g_is64;                           // 1 if edge_index is int64

// ---------------- packed fp32x2 helpers (Blackwell FFMA2 path) -------------
__device__ __forceinline__ u64 pack2(float x, float y) {
    u64 r; asm("mov.b64 %0, {%1, %2};" : "=l"(r) : "f"(x), "f"(y)); return r;
}
__device__ __forceinline__ float2 unpack2(u64 v) {
    float2 f; asm("mov.b64 {%0, %1}, %2;" : "=f"(f.x), "=f"(f.y) : "l"(v)); return f;
}
__device__ __forceinline__ void ffma2(u64& d, u64 a, u64 b) {
    asm("fma.rn.f32x2 %0, %1, %2, %3;" : "=l"(d) : "l"(a), "l"(b), "l"(d));
}

// ---------------- K-1: detect index dtype + zero degree counts -------------
// If int64: odd 32-bit words in [0, 2*EE) are src high words -> all 0.
// If int32: random node indices; 4096 samples all-zero is impossible.
__global__ void k_detect(const unsigned* __restrict__ ei_w) {
    __shared__ int s_nz;
    if (threadIdx.x == 0) s_nz = 0;
    __syncthreads();
    int nz = 0;
    for (int i = threadIdx.x; i < 4096; i += blockDim.x) {
        unsigned pos = 2u * (unsigned)((long long)i * (EE - 1) / 4095) + 1u;
        if (ei_w[pos] != 0u) nz = 1;
    }
    if (nz) atomicOr(&s_nz, 1);
    for (int i = threadIdx.x; i < NN; i += blockDim.x) g_cnt[i] = 0;
    __syncthreads();
    if (threadIdx.x == 0) g_is64 = s_nz ? 0 : 1;
}

// ---------------- K0: normalize edge indices + count in-degrees ------------
__global__ void k_prep(const void* __restrict__ ei) {
    int i = blockIdx.x * blockDim.x + threadIdx.x;
    if (i >= EE) return;
    int s, d;
    if (g_is64) {
        const long long* p = (const long long*)ei;
        s = (int)p[i];
        d = (int)p[EE + i];
    } else {
        const int* p = (const int*)ei;
        s = p[i];
        d = p[EE + i];
    }
    g_src[i] = s;
    g_dst[i] = d;
    atomicAdd(&g_cnt[d], 1);
}

// ---------------- K0b: exclusive scan of degrees -> row_ptr + cursors ------
__global__ void k_scan() {
    __shared__ int ssum[1024];
    const int SEG = (NN + 1023) / 1024;  // 49
    int t = threadIdx.x;
    int b0 = t * SEG;
    int sum = 0;
    for (int i = 0; i < SEG; i++) {
        int n = b0 + i;
        if (n < NN) sum += g_cnt[n];
    }
    ssum[t] = sum;
    __syncthreads();
    for (int o = 1; o < 1024; o <<= 1) {
        int u = (t >= o) ? ssum[t - o] : 0;
        __syncthreads();
        ssum[t] += u;
        __syncthreads();
    }
    int off = ssum[t] - sum;  // exclusive prefix for this thread's segment
    for (int i = 0; i < SEG; i++) {
        int n = b0 + i;
        if (n < NN) {
            g_rowp[n] = off;
            g_cur[n] = off;
            off += g_cnt[n];
        }
    }
    if (t == 0) g_rowp[NN] = EE;
}

// ---------------- K0c: fill CSR adjacency ----------------------------------
__global__ void k_fill() {
    int e = blockIdx.x * blockDim.x + threadIdx.x;
    if (e >= EE) return;
    int d = g_dst[e];
    int slot = atomicAdd(&g_cur[d], 1);
    g_adj[slot] = g_src[e];
}

// ---------------- K1: fused 3x GEMM from x (K=128, 3 weights 128x64) -------
__global__ __launch_bounds__(512) void k_gemm1(
    const float* __restrict__ x, const float* __restrict__ Wl1,
    const float* __restrict__ Wr1, const float* __restrict__ Wlin) {
    extern __shared__ float sm[];
    float* sW = sm;                 // 3 * 128 * 64
    float* sx = sm + 3 * FF * HH;   // 16 warps * 4 rows * 128
    int tid = threadIdx.x;
    for (int i = tid; i < FF * HH; i += blockDim.x) {
        sW[i]               = Wl1[i];
        sW[FF * HH + i]     = Wr1[i];
        sW[2 * FF * HH + i] = Wlin[i];  // rows 0..127 of Wlin
    }
    __syncthreads();
    int warp = tid >> 5, lane = tid & 31;
    int q = lane >> 3, li = lane & 7;
    float* sxw = sx + warp * (4 * FF);
    int nw = (gridDim.x * blockDim.x) >> 5;
    int gw = (blockIdx.x * blockDim.x + tid) >> 5;
    for (int grp = gw; grp < NN / 4; grp += nw) {
        int r0 = grp * 4;
        const float4* xv = reinterpret_cast<const float4*>(x + (size_t)r0 * FF);
        float4* sxv = reinterpret_cast<float4*>(sxw);
#pragma unroll
        for (int j = 0; j < 4; j++) sxv[lane + 32 * j] = xv[lane + 32 * j];
        __syncwarp();
        u64 acc[3][4];
#pragma unroll
        for (int w = 0; w < 3; w++)
#pragma unroll
            for (int j = 0; j < 4; j++) acc[w][j] = 0ull;
        const float* xr = sxw + q * FF;
#pragma unroll 8
        for (int k = 0; k < FF; k++) {
            float xk = xr[k];
            u64 xk2 = pack2(xk, xk);
#pragma unroll
            for (int w = 0; w < 3; w++) {
                const ulonglong2* wp = reinterpret_cast<const ulonglong2*>(
                    sW + w * FF * HH + k * HH + li * 8);
                ulonglong2 wa = wp[0], wb = wp[1];
                ffma2(acc[w][0], xk2, wa.x);
                ffma2(acc[w][1], xk2, wa.y);
                ffma2(acc[w][2], xk2, wb.x);
                ffma2(acc[w][3], xk2, wb.y);
            }
        }
        int row = r0 + q;
        float* outs[3] = {g_y1, g_z1, g_xa};
#pragma unroll
        for (int w = 0; w < 3; w++) {
            ulonglong2* op = reinterpret_cast<ulonglong2*>(
                outs[w] + (size_t)row * HH + li * 8);
            ulonglong2 o0; o0.x = acc[w][0]; o0.y = acc[w][1];
            ulonglong2 o1; o1.x = acc[w][2]; o1.y = acc[w][3];
            op[0] = o0;
            op[1] = o1;
        }
        __syncwarp();
    }
}

// ---------------- K2: conv1 aggregate (gather) + epilogue, warp per node ---
// hid[n] = relu(l2norm(mean_{s in adj(n)} y1[s] + bl1 + z1[n]))
__global__ void k_conv1(const float* __restrict__ bl1) {
    int gt = blockIdx.x * blockDim.x + threadIdx.x;
    int n = gt >> 5, lane = gt & 31;
    if (n >= NN) return;
    int beg = g_rowp[n], end = g_rowp[n + 1];
    int col = 2 * lane;
    float a0 = 0.f, a1 = 0.f;
    for (int base = beg; base < end; base += 32) {
        int s_l = (base + lane < end) ? g_adj[base + lane] : 0;
        int cnt = min(end - base, 32);
        for (int j = 0; j < cnt; j++) {
            int s = __shfl_sync(0xffffffffu, s_l, j);
            float2 v = *reinterpret_cast<const float2*>(g_y1 + (size_t)s * HH + col);
            a0 += v.x;
            a1 += v.y;
        }
    }
    int deg = end - beg;
    float invc = 1.f / (float)max(deg, 1);
    float2 zb = *reinterpret_cast<const float2*>(g_z1 + (size_t)n * HH + col);
    float2 bb = *reinterpret_cast<const float2*>(bl1 + col);
    float v0 = a0 * invc + bb.x + zb.x;
    float v1 = a1 * invc + bb.y + zb.y;
    float s = v0 * v0 + v1 * v1;
#pragma unroll
    for (int o = 16; o > 0; o >>= 1) s += __shfl_xor_sync(0xffffffffu, s, o);
    float inv = 1.f / fmaxf(sqrtf(s), 1e-12f);
    *reinterpret_cast<float2*>(g_hid + (size_t)n * HH + col) =
        make_float2(fmaxf(v0 * inv, 0.f), fmaxf(v1 * inv, 0.f));
}

// ---------------- K3: h = relu(xa + hid @ Wlin[128:] + blin) ---------------
__global__ __launch_bounds__(512) void k_lin1(
    const float* __restrict__ Wlin, const float* __restrict__ blin) {
    __shared__ float sB[HH * HH];
    __shared__ float sb[HH];
    __shared__ float sx[16 * 4 * HH];
    int tid = threadIdx.x;
    for (int i = tid; i < HH * HH; i += blockDim.x) sB[i] = Wlin[FF * HH + i];
    if (tid < HH) sb[tid] = blin[tid];
    __syncthreads();
    int warp = tid >> 5, lane = tid & 31;
    int q = lane >> 3, li = lane & 7;
    float* sxw = sx + warp * (4 * HH);
    int nw = (gridDim.x * blockDim.x) >> 5;
    int gw = (blockIdx.x * blockDim.x + tid) >> 5;
    for (int grp = gw; grp < NN / 4; grp += nw) {
        int r0 = grp * 4;
        const float4* hv = reinterpret_cast<const float4*>(g_hid + (size_t)r0 * HH);
        float4* sxv = reinterpret_cast<float4*>(sxw);
        sxv[lane] = hv[lane];
        sxv[lane + 32] = hv[lane + 32];
        __syncwarp();
        u64 acc[4];
#pragma unroll
        for (int j = 0; j < 4; j++) acc[j] = 0ull;
        const float* xr = sxw + q * HH;
#pragma unroll 8
        for (int k = 0; k < HH; k++) {
            float xk = xr[k];
            u64 xk2 = pack2(xk, xk);
            const ulonglong2* wp =
                reinterpret_cast<const ulonglong2*>(sB + k * HH + li * 8);
            ulonglong2 wa = wp[0], wb = wp[1];
            ffma2(acc[0], xk2, wa.x);
            ffma2(acc[1], xk2, wa.y);
            ffma2(acc[2], xk2, wb.x);
            ffma2(acc[3], xk2, wb.y);
        }
        int row = r0 + q;
        const float* xap = g_xa + (size_t)row * HH + li * 8;
        float* hp = g_h + (size_t)row * HH + li * 8;
#pragma unroll
        for (int j = 0; j < 4; j++) {
            float2 a = unpack2(acc[j]);
            hp[2 * j]     = fmaxf(a.x + xap[2 * j]     + sb[li * 8 + 2 * j],     0.f);
            hp[2 * j + 1] = fmaxf(a.y + xap[2 * j + 1] + sb[li * 8 + 2 * j + 1], 0.f);
        }
        __syncwarp();
    }
}

// ---------------- K4: y2 = h @ Wl2, z2 = h @ Wr2 (K=64, 80 fused cols) -----
__global__ __launch_bounds__(512) void k_gemm2(
    const float* __restrict__ Wl2, const float* __restrict__ Wr2) {
    __shared__ float sW[HH * 80];  // [k][0:40)=Wl2, [k][40:80)=Wr2
    __shared__ float sx[16 * 4 * HH];
    int tid = threadIdx.x;
    for (int i = tid; i < HH * CC; i += blockDim.x) {
        int k = i / CC, c = i - k * CC;
        sW[k * 80 + c]      = Wl2[i];
        sW[k * 80 + 40 + c] = Wr2[i];
    }
    __syncthreads();
    int warp = tid >> 5, lane = tid & 31;
    int q = lane >> 3, li = lane & 7;
    int c0 = li * 10;
    float* sxw = sx + warp * (4 * HH);
    int nw = (gridDim.x * blockDim.x) >> 5;
    int gw = (blockIdx.x * blockDim.x + tid) >> 5;
    for (int grp = gw; grp < NN / 4; grp += nw) {
        int r0 = grp * 4;
        const float4* hv = reinterpret_cast<const float4*>(g_h + (size_t)r0 * HH);
        float4* sxv = reinterpret_cast<float4*>(sxw);
        sxv[lane] = hv[lane];
        sxv[lane + 32] = hv[lane + 32];
        __syncwarp();
        u64 acc[5];
#pragma unroll
        for (int j = 0; j < 5; j++) acc[j] = 0ull;
        const float* xr = sxw + q * HH;
#pragma unroll 8
        for (int k = 0; k < HH; k++) {
            float xk = xr[k];
            u64 xk2 = pack2(xk, xk);
            const u64* wp = reinterpret_cast<const u64*>(sW + k * 80 + c0);
#pragma unroll
            for (int t = 0; t < 5; t++) ffma2(acc[t], xk2, wp[t]);
        }
        int row = r0 + q;
        float* dp = (li < 4) ? (g_y2 + (size_t)row * CC + c0)
                             : (g_z2 + (size_t)row * CC + (c0 - 40));
#pragma unroll
        for (int t = 0; t < 5; t++) {
            float2 a = unpack2(acc[t]);
            *reinterpret_cast<float2*>(dp + 2 * t) = a;
        }
        __syncwarp();
    }
}

// ---------------- K5: conv2 aggregate (gather) + l2norm, warp per node -----
// out[n] = l2norm(mean_{s in adj(n)} y2[s] + bl2 + z2[n])
__global__ void k_conv2(const float* __restrict__ bl2, float* __restrict__ out) {
    int gt = blockIdx.x * blockDim.x + threadIdx.x;
    int n = gt >> 5, lane = gt & 31;
    if (n >= NN) return;
    int beg = g_rowp[n], end = g_rowp[n + 1];
    int col = 2 * lane;               // valid for lane < 20
    bool act = (col < CC);
    float a0 = 0.f, a1 = 0.f;
    for (int base = beg; base < end; base += 32) {
        int s_l = (base + lane < end) ? g_adj[base + lane] : 0;
        int cnt = min(end - base, 32);
        for (int j = 0; j < cnt; j++) {
            int s = __shfl_sync(0xffffffffu, s_l, j);
            if (act) {
                float2 v = *reinterpret_cast<const float2*>(g_y2 + (size_t)s * CC + col);
                a0 += v.x;
                a1 += v.y;
            }
        }
    }
    int deg = end - beg;
    float invc = 1.f / (float)max(deg, 1);
    float v0 = 0.f, v1 = 0.f;
    if (act) {
        float2 zb = *reinterpret_cast<const float2*>(g_z2 + (size_t)n * CC + col);
        float2 bb = *reinterpret_cast<const float2*>(bl2 + col);
        v0 = a0 * invc + bb.x + zb.x;
        v1 = a1 * invc + bb.y + zb.y;
    }
    float s = v0 * v0 + v1 * v1;
#pragma unroll
    for (int o = 16; o > 0; o >>= 1) s += __shfl_xor_sync(0xffffffffu, s, o);
    float inv = 1.f / fmaxf(sqrtf(s), 1e-12f);
    if (act)
        *reinterpret_cast<float2*>(out + (size_t)n * CC + col) =
            make_float2(v0 * inv, v1 * inv);
}

// ---------------------------------------------------------------------------
extern "C" void kernel_launch(void* const* d_in, const int* in_sizes, int n_in,
                              void* d_out, int out_size) {
    const float* x    = (const float*)d_in[0];
    const void*  ei   = d_in[1];               // int32 or int64, detected on-device
    const float* Wl1  = (const float*)d_in[2];
    const float* bl1  = (const float*)d_in[3];
    const float* Wr1  = (const float*)d_in[4];
    const float* Wlin = (const float*)d_in[5];
    const float* blin = (const float*)d_in[6];
    const float* Wl2  = (const float*)d_in[7];
    const float* bl2  = (const float*)d_in[8];
    const float* Wr2  = (const float*)d_in[9];
    float* out = (float*)d_out;

    const int smem1 = (3 * FF * HH + 16 * 4 * FF) * (int)sizeof(float);  // 128 KB
    cudaFuncSetAttribute(k_gemm1, cudaFuncAttributeMaxDynamicSharedMemorySize, smem1);

    k_detect<<<1, 1024>>>((const unsigned*)ei);
    k_prep<<<3125, 256>>>(ei);
    k_scan<<<1, 1024>>>();
    k_fill<<<3125, 256>>>();
    k_gemm1<<<148, 512, smem1>>>(x, Wl1, Wr1, Wlin);
    k_conv1<<<6250, 256>>>(bl1);
    k_lin1<<<782, 512>>>(Wlin, blin);
    k_gemm2<<<782, 512>>>(Wl2, Wr2);
    k_conv2<<<6250, 256>>>(bl2, out);
}

// round 13
// speedup vs baseline: 1.5214x; 1.5214x over previous
#include <cuda_runtime.h>

#define NN 50000
#define EE 800000
#define FF 128
#define HH 64
#define CC 40

typedef unsigned long long u64;

// ---------------- scratch (device globals: no allocation allowed) ----------
__device__ __align__(16) float g_y1[NN * HH];    // x @ Wl1
__device__ __align__(16) float g_z1[NN * HH];    // x @ Wr1
__device__ __align__(16) float g_xa[NN * HH];    // x @ Wlin[0:128]
__device__ __align__(16) float g_agg1[NN * HH];  // scatter-sum of y1[src] by dst
__device__ __align__(16) float g_hid[NN * HH];   // relu(l2norm(mean + bl1 + z1))
__device__ __align__(16) float g_h[NN * HH];     // relu(xa + hid @ Wlin[128:] + blin)
__device__ __align__(16) float g_y2[NN * CC];    // h @ Wl2
__device__ __align__(16) float g_z2[NN * CC];    // h @ Wr2
__device__ __align__(16) float g_agg2[NN * CC];  // scatter-sum of y2[src] by dst
__device__ int g_cnt[NN];                        // in-degree
__device__ int g_src[EE];                        // normalized int32 src
__device__ int g_dst[EE];                        // normalized int32 dst
__device__ int g_is64;                           // 1 if edge_index is int64

// ---------------- packed fp32x2 helpers (Blackwell FFMA2 path) -------------
__device__ __forceinline__ u64 pack2(float x, float y) {
    u64 r; asm("mov.b64 %0, {%1, %2};" : "=l"(r) : "f"(x), "f"(y)); return r;
}
__device__ __forceinline__ float2 unpack2(u64 v) {
    float2 f; asm("mov.b64 {%0, %1}, %2;" : "=f"(f.x), "=f"(f.y) : "l"(v)); return f;
}
__device__ __forceinline__ void ffma2(u64& d, u64 a, u64 b) {
    asm("fma.rn.f32x2 %0, %1, %2, %3;" : "=l"(d) : "l"(a), "l"(b), "l"(d));
}

__device__ __forceinline__ void red_add_v4(float* p, float4 v) {
    asm volatile("red.global.add.v4.f32 [%0], {%1, %2, %3, %4};"
                 :: "l"(p), "f"(v.x), "f"(v.y), "f"(v.z), "f"(v.w)
                 : "memory");
}

// ---------------- K1: detect index dtype -----------------------------------
// If int64: odd 32-bit words in [0, 2*EE) are src high words -> all 0.
// If int32: random node indices; 4096 samples all-zero is impossible.
__global__ void k_detect(const unsigned* __restrict__ ei_w) {
    __shared__ int s_nz;
    if (threadIdx.x == 0) s_nz = 0;
    __syncthreads();
    int nz = 0;
    for (int i = threadIdx.x; i < 4096; i += blockDim.x) {
        unsigned pos = 2u * (unsigned)((long long)i * (EE - 1) / 4095) + 1u;
        if (ei_w[pos] != 0u) nz = 1;
    }
    if (nz) atomicOr(&s_nz, 1);
    __syncthreads();
    if (threadIdx.x == 0) g_is64 = s_nz ? 0 : 1;
}

// ---------------- K2: zero accumulators ------------------------------------
__global__ void k_zero() {
    int i = blockIdx.x * blockDim.x + threadIdx.x;
    float4 z = make_float4(0.f, 0.f, 0.f, 0.f);
    if (i < NN * HH / 4) reinterpret_cast<float4*>(g_agg1)[i] = z;
    if (i < NN * CC / 4) reinterpret_cast<float4*>(g_agg2)[i] = z;
    if (i < NN) g_cnt[i] = 0;
}

// ---------------- K3: normalize edge indices to int32 ----------------------
__global__ void k_prep(const void* __restrict__ ei) {
    int i = blockIdx.x * blockDim.x + threadIdx.x;
    if (i >= EE) return;
    if (g_is64) {
        const long long* p = (const long long*)ei;
        g_src[i] = (int)p[i];
        g_dst[i] = (int)p[EE + i];
    } else {
        const int* p = (const int*)ei;
        g_src[i] = p[i];
        g_dst[i] = p[EE + i];
    }
}

// ---------------- K4: fused 3x GEMM from x (K=128, 3 weights 128x64) -------
// 8 rows per warp, 2 rows per thread (rows r0+q and r0+q+4), FFMA2 math.
__global__ __launch_bounds__(512) void k_gemm1(
    const float* __restrict__ x, const float* __restrict__ Wl1,
    const float* __restrict__ Wr1, const float* __restrict__ Wlin) {
    extern __shared__ float sm[];
    float* sW = sm;                 // 3 * 128 * 64 = 24576 floats
    float* sx = sm + 3 * FF * HH;   // 16 warps * 8 rows * 128 = 16384 floats
    int tid = threadIdx.x;
    for (int i = tid; i < FF * HH; i += blockDim.x) {
        sW[i]               = Wl1[i];
        sW[FF * HH + i]     = Wr1[i];
        sW[2 * FF * HH + i] = Wlin[i];  // rows 0..127 of Wlin
    }
    __syncthreads();
    int warp = tid >> 5, lane = tid & 31;
    int q = lane >> 3, li = lane & 7;
    float* sxw = sx + warp * (8 * FF);
    int nw = (gridDim.x * blockDim.x) >> 5;
    int gw = (blockIdx.x * blockDim.x + tid) >> 5;
    for (int grp = gw; grp < NN / 8; grp += nw) {
        int r0 = grp * 8;
        const float4* xv = reinterpret_cast<const float4*>(x + (size_t)r0 * FF);
        float4* sxv = reinterpret_cast<float4*>(sxw);
#pragma unroll
        for (int j = 0; j < 8; j++) sxv[lane + 32 * j] = xv[lane + 32 * j];
        __syncwarp();
        u64 acc[3][4][2];
#pragma unroll
        for (int w = 0; w < 3; w++)
#pragma unroll
            for (int j = 0; j < 4; j++) { acc[w][j][0] = 0ull; acc[w][j][1] = 0ull; }
        const float* xra = sxw + q * FF;
        const float* xrb = sxw + (q + 4) * FF;
#pragma unroll 4
        for (int k = 0; k < FF; k++) {
            float xa = xra[k], xb = xrb[k];
            u64 xa2 = pack2(xa, xa);
            u64 xb2 = pack2(xb, xb);
#pragma unroll
            for (int w = 0; w < 3; w++) {
                const ulonglong2* wp = reinterpret_cast<const ulonglong2*>(
                    sW + w * FF * HH + k * HH + li * 8);
                ulonglong2 wa = wp[0], wb = wp[1];
                ffma2(acc[w][0][0], xa2, wa.x);
                ffma2(acc[w][1][0], xa2, wa.y);
                ffma2(acc[w][2][0], xa2, wb.x);
                ffma2(acc[w][3][0], xa2, wb.y);
                ffma2(acc[w][0][1], xb2, wa.x);
                ffma2(acc[w][1][1], xb2, wa.y);
                ffma2(acc[w][2][1], xb2, wb.x);
                ffma2(acc[w][3][1], xb2, wb.y);
            }
        }
        float* outs[3] = {g_y1, g_z1, g_xa};
#pragma unroll
        for (int w = 0; w < 3; w++) {
#pragma unroll
            for (int r = 0; r < 2; r++) {
                int row = r0 + q + 4 * r;
                ulonglong2* op = reinterpret_cast<ulonglong2*>(
                    outs[w] + (size_t)row * HH + li * 8);
                ulonglong2 o0; o0.x = acc[w][0][r]; o0.y = acc[w][1][r];
                ulonglong2 o1; o1.x = acc[w][2][r]; o1.y = acc[w][3][r];
                op[0] = o0;
                op[1] = o1;
            }
        }
        __syncwarp();
    }
}

// ---------------- K5: conv1 scatter (64 floats/edge, vectorized L2 red) ----
__global__ void k_scatter1() {
    unsigned idx = blockIdx.x * blockDim.x + threadIdx.x;
    if (idx >= (unsigned)EE * 16u) return;
    unsigned e = idx >> 4, c = idx & 15;
    int s = g_src[e];
    int d = g_dst[e];
    float4 v = reinterpret_cast<const float4*>(g_y1 + (size_t)s * HH)[c];
    red_add_v4(g_agg1 + (size_t)d * HH + c * 4, v);
    if (c == 0) atomicAdd(&g_cnt[d], 1);
}

// ---------------- K6: hidden = relu(l2norm(agg1/cnt + bl1 + z1)) -----------
__global__ void k_hidden(const float* __restrict__ bl1) {
    int gt = blockIdx.x * blockDim.x + threadIdx.x;
    int n = gt >> 5, lane = gt & 31;
    if (n >= NN) return;
    float invc = 1.f / (float)max(g_cnt[n], 1);
    size_t b = (size_t)n * HH;
    float v0 = g_agg1[b + lane] * invc + bl1[lane] + g_z1[b + lane];
    float v1 = g_agg1[b + 32 + lane] * invc + bl1[32 + lane] + g_z1[b + 32 + lane];
    float s = v0 * v0 + v1 * v1;
#pragma unroll
    for (int o = 16; o > 0; o >>= 1) s += __shfl_xor_sync(0xffffffffu, s, o);
    float inv = 1.f / fmaxf(sqrtf(s), 1e-12f);
    g_hid[b + lane]      = fmaxf(v0 * inv, 0.f);
    g_hid[b + 32 + lane] = fmaxf(v1 * inv, 0.f);
}

// ---------------- K7: h = relu(xa + hid @ Wlin[128:] + blin) ---------------
__global__ __launch_bounds__(512) void k_lin1(
    const float* __restrict__ Wlin, const float* __restrict__ blin) {
    __shared__ float sB[HH * HH];
    __shared__ float sb[HH];
    __shared__ float sx[16 * 4 * HH];
    int tid = threadIdx.x;
    for (int i = tid; i < HH * HH; i += blockDim.x) sB[i] = Wlin[FF * HH + i];
    if (tid < HH) sb[tid] = blin[tid];
    __syncthreads();
    int warp = tid >> 5, lane = tid & 31;
    int q = lane >> 3, li = lane & 7;
    float* sxw = sx + warp * (4 * HH);
    int nw = (gridDim.x * blockDim.x) >> 5;
    int gw = (blockIdx.x * blockDim.x + tid) >> 5;
    for (int grp = gw; grp < NN / 4; grp += nw) {
        int r0 = grp * 4;
        const float4* hv = reinterpret_cast<const float4*>(g_hid + (size_t)r0 * HH);
        float4* sxv = reinterpret_cast<float4*>(sxw);
        sxv[lane] = hv[lane];
        sxv[lane + 32] = hv[lane + 32];
        __syncwarp();
        u64 acc[4];
#pragma unroll
        for (int j = 0; j < 4; j++) acc[j] = 0ull;
        const float* xr = sxw + q * HH;
#pragma unroll 8
        for (int k = 0; k < HH; k++) {
            float xk = xr[k];
            u64 xk2 = pack2(xk, xk);
            const ulonglong2* wp =
                reinterpret_cast<const ulonglong2*>(sB + k * HH + li * 8);
            ulonglong2 wa = wp[0], wb = wp[1];
            ffma2(acc[0], xk2, wa.x);
            ffma2(acc[1], xk2, wa.y);
            ffma2(acc[2], xk2, wb.x);
            ffma2(acc[3], xk2, wb.y);
        }
        int row = r0 + q;
        const float* xap = g_xa + (size_t)row * HH + li * 8;
        float* hp = g_h + (size_t)row * HH + li * 8;
#pragma unroll
        for (int j = 0; j < 4; j++) {
            float2 a = unpack2(acc[j]);
            hp[2 * j]     = fmaxf(a.x + xap[2 * j]     + sb[li * 8 + 2 * j],     0.f);
            hp[2 * j + 1] = fmaxf(a.y + xap[2 * j + 1] + sb[li * 8 + 2 * j + 1], 0.f);
        }
        __syncwarp();
    }
}

// ---------------- K8: y2 = h @ Wl2, z2 = h @ Wr2 (K=64, 80 fused cols) -----
__global__ __launch_bounds__(512) void k_gemm2(
    const float* __restrict__ Wl2, const float* __restrict__ Wr2) {
    __shared__ float sW[HH * 80];  // [k][0:40)=Wl2, [k][40:80)=Wr2
    __shared__ float sx[16 * 4 * HH];
    int tid = threadIdx.x;
    for (int i = tid; i < HH * CC; i += blockDim.x) {
        int k = i / CC, c = i - k * CC;
        sW[k * 80 + c]      = Wl2[i];
        sW[k * 80 + 40 + c] = Wr2[i];
    }
    __syncthreads();
    int warp = tid >> 5, lane = tid & 31;
    int q = lane >> 3, li = lane & 7;
    int c0 = li * 10;
    float* sxw = sx + warp * (4 * HH);
    int nw = (gridDim.x * blockDim.x) >> 5;
    int gw = (blockIdx.x * blockDim.x + tid) >> 5;
    for (int grp = gw; grp < NN / 4; grp += nw) {
        int r0 = grp * 4;
        const float4* hv = reinterpret_cast<const float4*>(g_h + (size_t)r0 * HH);
        float4* sxv = reinterpret_cast<float4*>(sxw);
        sxv[lane] = hv[lane];
        sxv[lane + 32] = hv[lane + 32];
        __syncwarp();
        u64 acc[5];
#pragma unroll
        for (int j = 0; j < 5; j++) acc[j] = 0ull;
        const float* xr = sxw + q * HH;
#pragma unroll 8
        for (int k = 0; k < HH; k++) {
            float xk = xr[k];
            u64 xk2 = pack2(xk, xk);
            const u64* wp = reinterpret_cast<const u64*>(sW + k * 80 + c0);
#pragma unroll
            for (int t = 0; t < 5; t++) ffma2(acc[t], xk2, wp[t]);
        }
        int row = r0 + q;
        float* dp = (li < 4) ? (g_y2 + (size_t)row * CC + c0)
                             : (g_z2 + (size_t)row * CC + (c0 - 40));
#pragma unroll
        for (int t = 0; t < 5; t++) {
            float2 a = unpack2(acc[t]);
            *reinterpret_cast<float2*>(dp + 2 * t) = a;
        }
        __syncwarp();
    }
}

// ---------------- K9: conv2 scatter (40 floats/edge) -----------------------
__global__ void k_scatter2() {
    unsigned idx = blockIdx.x * blockDim.x + threadIdx.x;
    if (idx >= (unsigned)EE * 10u) return;
    unsigned e = idx / 10u, c = idx - e * 10u;
    int s = g_src[e];
    int d = g_dst[e];
    float4 v = reinterpret_cast<const float4*>(g_y2 + (size_t)s * CC)[c];
    red_add_v4(g_agg2 + (size_t)d * CC + c * 4, v);
}

// ---------------- K10: out = l2norm(agg2/cnt + bl2 + z2) -------------------
__global__ void k_final(const float* __restrict__ bl2, float* __restrict__ out) {
    int gt = blockIdx.x * blockDim.x + threadIdx.x;
    int n = gt >> 5, lane = gt & 31;
    if (n >= NN) return;
    float invc = 1.f / (float)max(g_cnt[n], 1);
    size_t b = (size_t)n * CC;
    float v0 = g_agg2[b + lane] * invc + bl2[lane] + g_z2[b + lane];
    float v1 = 0.f;
    if (lane < 8)
        v1 = g_agg2[b + 32 + lane] * invc + bl2[32 + lane] + g_z2[b + 32 + lane];
    float s = v0 * v0 + v1 * v1;
#pragma unroll
    for (int o = 16; o > 0; o >>= 1) s += __shfl_xor_sync(0xffffffffu, s, o);
    float inv = 1.f / fmaxf(sqrtf(s), 1e-12f);
    out[b + lane] = v0 * inv;
    if (lane < 8) out[b + 32 + lane] = v1 * inv;
}

// ---------------------------------------------------------------------------
extern "C" void kernel_launch(void* const* d_in, const int* in_sizes, int n_in,
                              void* d_out, int out_size) {
    const float* x    = (const float*)d_in[0];
    const void*  ei   = d_in[1];               // int32 or int64, detected on-device
    const float* Wl1  = (const float*)d_in[2];
    const float* bl1  = (const float*)d_in[3];
    const float* Wr1  = (const float*)d_in[4];
    const float* Wlin = (const float*)d_in[5];
    const float* blin = (const float*)d_in[6];
    const float* Wl2  = (const float*)d_in[7];
    const float* bl2  = (const float*)d_in[8];
    const float* Wr2  = (const float*)d_in[9];
    float* out = (float*)d_out;

    const int smem1 = (3 * FF * HH + 16 * 8 * FF) * (int)sizeof(float);  // 160 KB
    cudaFuncSetAttribute(k_gemm1, cudaFuncAttributeMaxDynamicSharedMemorySize, smem1);

    k_detect<<<1, 1024>>>((const unsigned*)ei);   // launch 1
    k_zero<<<3125, 256>>>();                      // launch 2
    k_prep<<<3125, 256>>>(ei);                    // launch 3
    k_gemm1<<<148, 512, smem1>>>(x, Wl1, Wr1, Wlin);  // launch 4 <- ncu profiles this
    k_scatter1<<<50000, 256>>>();                 // E*16 work items exactly
    k_hidden<<<6250, 256>>>(bl1);                 // 50000 warps exactly
    k_lin1<<<782, 512>>>(Wlin, blin);
    k_gemm2<<<782, 512>>>(Wl2, Wr2);
    k_scatter2<<<31250, 256>>>();                 // E*10 work items exactly
    k_final<<<6250, 256>>>(bl2, out);
}

// round 14
// speedup vs baseline: 1.8460x; 1.2133x over previous
#include <cuda_runtime.h>

#define NN 50000
#define EE 800000
#define FF 128
#define HH 64
#define CC 40

typedef unsigned long long u64;

// ---------------- scratch (device globals: no allocation allowed) ----------
__device__ __align__(16) float g_y1[NN * HH];    // x @ Wl1
__device__ __align__(16) float g_z1[NN * HH];    // x @ Wr1
__device__ __align__(16) float g_xa[NN * HH];    // x @ Wlin[0:128]
__device__ __align__(16) float g_agg1[NN * HH];  // scatter-sum of y1[src] by dst
__device__ __align__(16) float g_hid[NN * HH];   // relu(l2norm(mean + bl1 + z1))
__device__ __align__(16) float g_y2[NN * CC];    // h @ Wl2
__device__ __align__(16) float g_z2[NN * CC];    // h @ Wr2
__device__ __align__(16) float g_agg2[NN * CC];  // scatter-sum of y2[src] by dst
__device__ int g_cnt[NN];                        // in-degree
__device__ int g_src[EE];                        // normalized int32 src
__device__ int g_dst[EE];                        // normalized int32 dst
__device__ int g_is64;                           // 1 if edge_index is int64

// ---------------- packed fp32x2 helpers (Blackwell FFMA2 path) -------------
__device__ __forceinline__ u64 pack2(float x, float y) {
    u64 r; asm("mov.b64 %0, {%1, %2};" : "=l"(r) : "f"(x), "f"(y)); return r;
}
__device__ __forceinline__ float2 unpack2(u64 v) {
    float2 f; asm("mov.b64 {%0, %1}, %2;" : "=f"(f.x), "=f"(f.y) : "l"(v)); return f;
}
__device__ __forceinline__ void ffma2(u64& d, u64 a, u64 b) {
    asm("fma.rn.f32x2 %0, %1, %2, %3;" : "=l"(d) : "l"(a), "l"(b), "l"(d));
}
__device__ __forceinline__ float getc(float4 v, int kk) {
    switch (kk) { case 0: return v.x; case 1: return v.y; case 2: return v.z; default: return v.w; }
}

__device__ __forceinline__ void red_add_v4(float* p, float4 v) {
    asm volatile("red.global.add.v4.f32 [%0], {%1, %2, %3, %4};"
                 :: "l"(p), "f"(v.x), "f"(v.y), "f"(v.z), "f"(v.w)
                 : "memory");
}

// ---------------- K1: detect index dtype -----------------------------------
__global__ void k_detect(const unsigned* __restrict__ ei_w) {
    __shared__ int s_nz;
    if (threadIdx.x == 0) s_nz = 0;
    __syncthreads();
    int nz = 0;
    for (int i = threadIdx.x; i < 4096; i += blockDim.x) {
        unsigned pos = 2u * (unsigned)((long long)i * (EE - 1) / 4095) + 1u;
        if (ei_w[pos] != 0u) nz = 1;
    }
    if (nz) atomicOr(&s_nz, 1);
    __syncthreads();
    if (threadIdx.x == 0) g_is64 = s_nz ? 0 : 1;
}

// ---------------- K2: zero accumulators ------------------------------------
__global__ void k_zero() {
    int i = blockIdx.x * blockDim.x + threadIdx.x;
    float4 z = make_float4(0.f, 0.f, 0.f, 0.f);
    if (i < NN * HH / 4) reinterpret_cast<float4*>(g_agg1)[i] = z;
    if (i < NN * CC / 4) reinterpret_cast<float4*>(g_agg2)[i] = z;
    if (i < NN) g_cnt[i] = 0;
}

// ---------------- K3: normalize edge indices to int32 ----------------------
__global__ void k_prep(const void* __restrict__ ei) {
    int i = blockIdx.x * blockDim.x + threadIdx.x;
    if (i >= EE) return;
    if (g_is64) {
        const long long* p = (const long long*)ei;
        g_src[i] = (int)p[i];
        g_dst[i] = (int)p[EE + i];
    } else {
        const int* p = (const int*)ei;
        g_src[i] = p[i];
        g_dst[i] = p[EE + i];
    }
}

// ---------------- K4: fused 3x GEMM from x (K=128, 3 weights 128x64) -------
// 16 rows per warp, 4 rows per thread; one weight matrix per pass (reg-safe).
// lane: q = lane>>3 -> 4 row-quads; li = lane&7 -> 8-col slice of 64.
__global__ __launch_bounds__(384) void k_gemm1(
    const float* __restrict__ x, const float* __restrict__ Wl1,
    const float* __restrict__ Wr1, const float* __restrict__ Wlin) {
    extern __shared__ float sm[];
    float* sW = sm;                 // 3 * 128 * 64 = 24576 floats (96 KB)
    float* sx = sm + 3 * FF * HH;   // 12 warps * 16 rows * 128 = 24576 floats (96 KB)
    int tid = threadIdx.x;
    for (int i = tid; i < FF * HH; i += blockDim.x) {
        sW[i]               = Wl1[i];
        sW[FF * HH + i]     = Wr1[i];
        sW[2 * FF * HH + i] = Wlin[i];  // rows 0..127 of Wlin
    }
    __syncthreads();
    int warp = tid >> 5, lane = tid & 31;
    int q = lane >> 3, li = lane & 7;
    float* sxw = sx + warp * (16 * FF);
    const float* xq = sxw + (q * 4) * FF;   // this thread's 4 rows
    int nw = (gridDim.x * blockDim.x) >> 5;
    int gw = (blockIdx.x * blockDim.x + tid) >> 5;
    float* const outs[3] = {g_y1, g_z1, g_xa};
    for (int grp = gw; grp < NN / 16; grp += nw) {
        int r0 = grp * 16;
        const float4* xv = reinterpret_cast<const float4*>(x + (size_t)r0 * FF);
        float4* sxv = reinterpret_cast<float4*>(sxw);
#pragma unroll
        for (int j = 0; j < 16; j++) sxv[lane + 32 * j] = xv[lane + 32 * j];
        __syncwarp();
#pragma unroll
        for (int w = 0; w < 3; w++) {
            u64 acc[4][4];  // [col-pair j][row r]
#pragma unroll
            for (int j = 0; j < 4; j++)
#pragma unroll
                for (int r = 0; r < 4; r++) acc[j][r] = 0ull;
            const float* wbase = sW + w * FF * HH + li * 8;
            for (int k = 0; k < FF; k += 4) {
                float4 xr[4];
#pragma unroll
                for (int r = 0; r < 4; r++)
                    xr[r] = *reinterpret_cast<const float4*>(xq + r * FF + k);
#pragma unroll
                for (int kk = 0; kk < 4; kk++) {
                    u64 xp[4];
#pragma unroll
                    for (int r = 0; r < 4; r++) {
                        float f = getc(xr[r], kk);
                        xp[r] = pack2(f, f);
                    }
                    const ulonglong2* wp = reinterpret_cast<const ulonglong2*>(
                        wbase + (k + kk) * HH);
                    ulonglong2 wa = wp[0], wb = wp[1];
#pragma unroll
                    for (int r = 0; r < 4; r++) {
                        ffma2(acc[0][r], xp[r], wa.x);
                        ffma2(acc[1][r], xp[r], wa.y);
                        ffma2(acc[2][r], xp[r], wb.x);
                        ffma2(acc[3][r], xp[r], wb.y);
                    }
                }
            }
#pragma unroll
            for (int r = 0; r < 4; r++) {
                int row = r0 + q * 4 + r;
                ulonglong2* op = reinterpret_cast<ulonglong2*>(
                    outs[w] + (size_t)row * HH + li * 8);
                ulonglong2 o0; o0.x = acc[0][r]; o0.y = acc[1][r];
                ulonglong2 o1; o1.x = acc[2][r]; o1.y = acc[3][r];
                op[0] = o0;
                op[1] = o1;
            }
        }
        __syncwarp();
    }
}

// ---------------- K5: conv1 scatter (64 floats/edge, vectorized L2 red) ----
__global__ void k_scatter1() {
    unsigned idx = blockIdx.x * blockDim.x + threadIdx.x;
    if (idx >= (unsigned)EE * 16u) return;
    unsigned e = idx >> 4, c = idx & 15;
    int s = g_src[e];
    int d = g_dst[e];
    float4 v = reinterpret_cast<const float4*>(g_y1 + (size_t)s * HH)[c];
    red_add_v4(g_agg1 + (size_t)d * HH + c * 4, v);
    if (c == 0) atomicAdd(&g_cnt[d], 1);
}

// ---------------- K6: hidden = relu(l2norm(agg1/cnt + bl1 + z1)) -----------
__global__ void k_hidden(const float* __restrict__ bl1) {
    int gt = blockIdx.x * blockDim.x + threadIdx.x;
    int n = gt >> 5, lane = gt & 31;
    if (n >= NN) return;
    float invc = 1.f / (float)max(g_cnt[n], 1);
    size_t b = (size_t)n * HH;
    float v0 = g_agg1[b + lane] * invc + bl1[lane] + g_z1[b + lane];
    float v1 = g_agg1[b + 32 + lane] * invc + bl1[32 + lane] + g_z1[b + 32 + lane];
    float s = v0 * v0 + v1 * v1;
#pragma unroll
    for (int o = 16; o > 0; o >>= 1) s += __shfl_xor_sync(0xffffffffu, s, o);
    float inv = 1.f / fmaxf(sqrtf(s), 1e-12f);
    g_hid[b + lane]      = fmaxf(v0 * inv, 0.f);
    g_hid[b + 32 + lane] = fmaxf(v1 * inv, 0.f);
}

// ---------------- K7: fused lin1 + gemm2 -----------------------------------
// Phase A: h = relu(xa + hid @ Wlin[128:] + blin)   (h kept in SMEM per warp)
// Phase B: y2 = h @ Wl2, z2 = h @ Wr2
__global__ __launch_bounds__(256) void k_lin2(
    const float* __restrict__ Wlin, const float* __restrict__ blin,
    const float* __restrict__ Wl2, const float* __restrict__ Wr2) {
    __shared__ float sB[HH * HH];    // Wlin rows 128..191
    __shared__ float sW2[HH * 80];   // [k][0:40)=Wl2, [k][40:80)=Wr2
    __shared__ float sb[HH];
    __shared__ float sx[8 * 4 * HH]; // 8 warps * 4 rows * 64
    int tid = threadIdx.x;
    for (int i = tid; i < HH * HH; i += blockDim.x) sB[i] = Wlin[FF * HH + i];
    for (int i = tid; i < HH * CC; i += blockDim.x) {
        int k = i / CC, c = i - k * CC;
        sW2[k * 80 + c]      = Wl2[i];
        sW2[k * 80 + 40 + c] = Wr2[i];
    }
    if (tid < HH) sb[tid] = blin[tid];
    __syncthreads();
    int warp = tid >> 5, lane = tid & 31;
    int q = lane >> 3, li = lane & 7;
    float* sxw = sx + warp * (4 * HH);
    int nw = (gridDim.x * blockDim.x) >> 5;
    int gw = (blockIdx.x * blockDim.x + tid) >> 5;
    for (int grp = gw; grp < NN / 4; grp += nw) {
        int r0 = grp * 4;
        // stage hid rows
        const float4* hv = reinterpret_cast<const float4*>(g_hid + (size_t)r0 * HH);
        float4* sxv = reinterpret_cast<float4*>(sxw);
        sxv[lane] = hv[lane];
        sxv[lane + 32] = hv[lane + 32];
        __syncwarp();
        // ---- Phase A: lin over K=64 ----
        u64 acc[4];
#pragma unroll
        for (int j = 0; j < 4; j++) acc[j] = 0ull;
        {
            const float* xr = sxw + q * HH;
#pragma unroll 8
            for (int k = 0; k < HH; k++) {
                float xk = xr[k];
                u64 xk2 = pack2(xk, xk);
                const ulonglong2* wp =
                    reinterpret_cast<const ulonglong2*>(sB + k * HH + li * 8);
                ulonglong2 wa = wp[0], wb = wp[1];
                ffma2(acc[0], xk2, wa.x);
                ffma2(acc[1], xk2, wa.y);
                ffma2(acc[2], xk2, wb.x);
                ffma2(acc[3], xk2, wb.y);
            }
        }
        int row = r0 + q;
        float hf[8];
        {
            const float* xap = g_xa + (size_t)row * HH + li * 8;
#pragma unroll
            for (int j = 0; j < 4; j++) {
                float2 a = unpack2(acc[j]);
                hf[2 * j]     = fmaxf(a.x + xap[2 * j]     + sb[li * 8 + 2 * j],     0.f);
                hf[2 * j + 1] = fmaxf(a.y + xap[2 * j + 1] + sb[li * 8 + 2 * j + 1], 0.f);
            }
        }
        __syncwarp();  // all lanes done reading hid from sxw
        // overwrite sxw with h
        {
            float4* hp = reinterpret_cast<float4*>(sxw + q * HH + li * 8);
            hp[0] = make_float4(hf[0], hf[1], hf[2], hf[3]);
            hp[1] = make_float4(hf[4], hf[5], hf[6], hf[7]);
        }
        __syncwarp();
        // ---- Phase B: gemm2 over K=64, 80 fused cols ----
        int c0 = li * 10;
        u64 acc2[5];
#pragma unroll
        for (int j = 0; j < 5; j++) acc2[j] = 0ull;
        {
            const float* xr = sxw + q * HH;
#pragma unroll 8
            for (int k = 0; k < HH; k++) {
                float xk = xr[k];
                u64 xk2 = pack2(xk, xk);
                const u64* wp = reinterpret_cast<const u64*>(sW2 + k * 80 + c0);
#pragma unroll
                for (int t = 0; t < 5; t++) ffma2(acc2[t], xk2, wp[t]);
            }
        }
        float* dp = (li < 4) ? (g_y2 + (size_t)row * CC + c0)
                             : (g_z2 + (size_t)row * CC + (c0 - 40));
#pragma unroll
        for (int t = 0; t < 5; t++) {
            float2 a = unpack2(acc2[t]);
            *reinterpret_cast<float2*>(dp + 2 * t) = a;
        }
        __syncwarp();
    }
}

// ---------------- K8: conv2 scatter (40 floats/edge) -----------------------
__global__ void k_scatter2() {
    unsigned idx = blockIdx.x * blockDim.x + threadIdx.x;
    if (idx >= (unsigned)EE * 10u) return;
    unsigned e = idx / 10u, c = idx - e * 10u;
    int s = g_src[e];
    int d = g_dst[e];
    float4 v = reinterpret_cast<const float4*>(g_y2 + (size_t)s * CC)[c];
    red_add_v4(g_agg2 + (size_t)d * CC + c * 4, v);
}

// ---------------- K9: out = l2norm(agg2/cnt + bl2 + z2) --------------------
__global__ void k_final(const float* __restrict__ bl2, float* __restrict__ out) {
    int gt = blockIdx.x * blockDim.x + threadIdx.x;
    int n = gt >> 5, lane = gt & 31;
    if (n >= NN) return;
    float invc = 1.f / (float)max(g_cnt[n], 1);
    size_t b = (size_t)n * CC;
    float v0 = g_agg2[b + lane] * invc + bl2[lane] + g_z2[b + lane];
    float v1 = 0.f;
    if (lane < 8)
        v1 = g_agg2[b + 32 + lane] * invc + bl2[32 + lane] + g_z2[b + 32 + lane];
    float s = v0 * v0 + v1 * v1;
#pragma unroll
    for (int o = 16; o > 0; o >>= 1) s += __shfl_xor_sync(0xffffffffu, s, o);
    float inv = 1.f / fmaxf(sqrtf(s), 1e-12f);
    out[b + lane] = v0 * inv;
    if (lane < 8) out[b + 32 + lane] = v1 * inv;
}

// ---------------------------------------------------------------------------
extern "C" void kernel_launch(void* const* d_in, const int* in_sizes, int n_in,
                              void* d_out, int out_size) {
    const float* x    = (const float*)d_in[0];
    const void*  ei   = d_in[1];               // int32 or int64, detected on-device
    const float* Wl1  = (const float*)d_in[2];
    const float* bl1  = (const float*)d_in[3];
    const float* Wr1  = (const float*)d_in[4];
    const float* Wlin = (const float*)d_in[5];
    const float* blin = (const float*)d_in[6];
    const float* Wl2  = (const float*)d_in[7];
    const float* bl2  = (const float*)d_in[8];
    const float* Wr2  = (const float*)d_in[9];
    float* out = (float*)d_out;

    // k_gemm1: 96 KB weights + 12 warps * 16 rows * 128 floats = 192 KB total
    const int smem1 = (3 * FF * HH + 12 * 16 * FF) * (int)sizeof(float);
    cudaFuncSetAttribute(k_gemm1, cudaFuncAttributeMaxDynamicSharedMemorySize, smem1);

    k_detect<<<1, 1024>>>((const unsigned*)ei);        // launch 1
    k_zero<<<3125, 256>>>();                           // launch 2
    k_prep<<<3125, 256>>>(ei);                         // launch 3
    k_gemm1<<<148, 384, smem1>>>(x, Wl1, Wr1, Wlin);   // launch 4 <- ncu profiles this
    k_scatter1<<<50000, 256>>>();                      // E*16 work items exactly
    k_hidden<<<6250, 256>>>(bl1);                      // 50000 warps exactly
    k_lin2<<<1563, 256>>>(Wlin, blin, Wl2, Wr2);       // fused lin1 + gemm2
    k_scatter2<<<31250, 256>>>();                      // E*10 work items exactly
    k_final<<<6250, 256>>>(bl2, out);
}

// round 15
// speedup vs baseline: 1.8722x; 1.0142x over previous
#include <cuda_runtime.h>

#define NN 50000
#define EE 800000
#define FF 128
#define HH 64
#define CC 40

typedef unsigned long long u64;

// ---------------- scratch (device globals: no allocation allowed) ----------
__device__ __align__(16) float g_y1[NN * HH];    // x @ Wl1
__device__ __align__(16) float g_z1[NN * HH];    // x @ Wr1
__device__ __align__(16) float g_xa[NN * HH];    // x @ Wlin[0:128]
__device__ __align__(16) float g_agg1[NN * HH];  // scatter-sum of y1[src] by dst
__device__ __align__(16) float g_hid[NN * HH];   // relu(l2norm(mean + bl1 + z1))
__device__ __align__(16) float g_y2[NN * CC];    // h @ Wl2
__device__ __align__(16) float g_z2[NN * CC];    // h @ Wr2
__device__ __align__(16) float g_agg2[NN * CC];  // scatter-sum of y2[src] by dst
__device__ int g_cnt[NN];                        // in-degree
__device__ int g_src[EE];                        // normalized int32 src
__device__ int g_dst[EE];                        // normalized int32 dst
__device__ int g_is64;                           // 1 if edge_index is int64

// ---------------- packed fp32x2 helpers (Blackwell FFMA2 path) -------------
__device__ __forceinline__ u64 pack2(float x, float y) {
    u64 r; asm("mov.b64 %0, {%1, %2};" : "=l"(r) : "f"(x), "f"(y)); return r;
}
__device__ __forceinline__ float2 unpack2(u64 v) {
    float2 f; asm("mov.b64 {%0, %1}, %2;" : "=f"(f.x), "=f"(f.y) : "l"(v)); return f;
}
__device__ __forceinline__ void ffma2(u64& d, u64 a, u64 b) {
    asm("fma.rn.f32x2 %0, %1, %2, %3;" : "=l"(d) : "l"(a), "l"(b), "l"(d));
}
__device__ __forceinline__ float getc(float4 v, int kk) {
    switch (kk) { case 0: return v.x; case 1: return v.y; case 2: return v.z; default: return v.w; }
}

__device__ __forceinline__ void red_add_v4(float* p, float4 v) {
    asm volatile("red.global.add.v4.f32 [%0], {%1, %2, %3, %4};"
                 :: "l"(p), "f"(v.x), "f"(v.y), "f"(v.z), "f"(v.w)
                 : "memory");
}

// ---------------- K1: detect index dtype -----------------------------------
__global__ void k_detect(const unsigned* __restrict__ ei_w) {
    __shared__ int s_nz;
    if (threadIdx.x == 0) s_nz = 0;
    __syncthreads();
    int nz = 0;
    for (int i = threadIdx.x; i < 4096; i += blockDim.x) {
        unsigned pos = 2u * (unsigned)((long long)i * (EE - 1) / 4095) + 1u;
        if (ei_w[pos] != 0u) nz = 1;
    }
    if (nz) atomicOr(&s_nz, 1);
    __syncthreads();
    if (threadIdx.x == 0) g_is64 = s_nz ? 0 : 1;
}

// ---------------- K2: zero accumulators ------------------------------------
__global__ void k_zero() {
    int i = blockIdx.x * blockDim.x + threadIdx.x;
    float4 z = make_float4(0.f, 0.f, 0.f, 0.f);
    if (i < NN * HH / 4) reinterpret_cast<float4*>(g_agg1)[i] = z;
    if (i < NN * CC / 4) reinterpret_cast<float4*>(g_agg2)[i] = z;
    if (i < NN) g_cnt[i] = 0;
}

// ---------------- K3: normalize edge indices to int32 ----------------------
__global__ void k_prep(const void* __restrict__ ei) {
    int i = blockIdx.x * blockDim.x + threadIdx.x;
    if (i >= EE) return;
    if (g_is64) {
        const long long* p = (const long long*)ei;
        g_src[i] = (int)p[i];
        g_dst[i] = (int)p[EE + i];
    } else {
        const int* p = (const int*)ei;
        g_src[i] = p[i];
        g_dst[i] = p[EE + i];
    }
}

// ---------------- K4: fused 3x GEMM from x (K=128, 3 weights 128x64) -------
// 16 rows/warp, 4 rows/thread. x read straight from gmem (L1/L2 resident);
// SMEM holds only the 3 weight matrices (96 KB) -> 2 blocks/SM, 24 warps.
__global__ __launch_bounds__(384, 2) void k_gemm1(
    const float* __restrict__ x, const float* __restrict__ Wl1,
    const float* __restrict__ Wr1, const float* __restrict__ Wlin) {
    extern __shared__ float sW[];   // 3 * 128 * 64 = 24576 floats (96 KB)
    int tid = threadIdx.x;
    for (int i = tid; i < FF * HH; i += blockDim.x) {
        sW[i]               = Wl1[i];
        sW[FF * HH + i]     = Wr1[i];
        sW[2 * FF * HH + i] = Wlin[i];  // rows 0..127 of Wlin
    }
    __syncthreads();
    int lane = tid & 31;
    int q = lane >> 3, li = lane & 7;
    int nw = (gridDim.x * blockDim.x) >> 5;
    int gw = (blockIdx.x * blockDim.x + tid) >> 5;
    float* const outs[3] = {g_y1, g_z1, g_xa};
    for (int grp = gw; grp < NN / 16; grp += nw) {
        int r0 = grp * 16;
        const float4* xrow[4];
#pragma unroll
        for (int r = 0; r < 4; r++)
            xrow[r] = reinterpret_cast<const float4*>(
                x + (size_t)(r0 + q * 4 + r) * FF);
#pragma unroll
        for (int w = 0; w < 3; w++) {
            u64 acc[4][4];  // [col-pair j][row r]
#pragma unroll
            for (int j = 0; j < 4; j++)
#pragma unroll
                for (int r = 0; r < 4; r++) acc[j][r] = 0ull;
            const float* wbase = sW + w * FF * HH + li * 8;
#pragma unroll 2
            for (int k4 = 0; k4 < FF / 4; k4++) {
                float4 xr[4];
#pragma unroll
                for (int r = 0; r < 4; r++) xr[r] = xrow[r][k4];
#pragma unroll
                for (int kk = 0; kk < 4; kk++) {
                    u64 xp[4];
#pragma unroll
                    for (int r = 0; r < 4; r++) {
                        float f = getc(xr[r], kk);
                        xp[r] = pack2(f, f);
                    }
                    const ulonglong2* wp = reinterpret_cast<const ulonglong2*>(
                        wbase + (k4 * 4 + kk) * HH);
                    ulonglong2 wa = wp[0], wb = wp[1];
#pragma unroll
                    for (int r = 0; r < 4; r++) {
                        ffma2(acc[0][r], xp[r], wa.x);
                        ffma2(acc[1][r], xp[r], wa.y);
                        ffma2(acc[2][r], xp[r], wb.x);
                        ffma2(acc[3][r], xp[r], wb.y);
                    }
                }
            }
#pragma unroll
            for (int r = 0; r < 4; r++) {
                int row = r0 + q * 4 + r;
                ulonglong2* op = reinterpret_cast<ulonglong2*>(
                    outs[w] + (size_t)row * HH + li * 8);
                ulonglong2 o0; o0.x = acc[0][r]; o0.y = acc[1][r];
                ulonglong2 o1; o1.x = acc[2][r]; o1.y = acc[3][r];
                op[0] = o0;
                op[1] = o1;
            }
        }
    }
}

// ---------------- K5: conv1 scatter (64 floats/edge, vectorized L2 red) ----
__global__ void k_scatter1() {
    unsigned idx = blockIdx.x * blockDim.x + threadIdx.x;
    if (idx >= (unsigned)EE * 16u) return;
    unsigned e = idx >> 4, c = idx & 15;
    int s = g_src[e];
    int d = g_dst[e];
    float4 v = reinterpret_cast<const float4*>(g_y1 + (size_t)s * HH)[c];
    red_add_v4(g_agg1 + (size_t)d * HH + c * 4, v);
    if (c == 0) atomicAdd(&g_cnt[d], 1);
}

// ---------------- K6: hidden = relu(l2norm(agg1/cnt + bl1 + z1)) -----------
__global__ void k_hidden(const float* __restrict__ bl1) {
    int gt = blockIdx.x * blockDim.x + threadIdx.x;
    int n = gt >> 5, lane = gt & 31;
    if (n >= NN) return;
    float invc = 1.f / (float)max(g_cnt[n], 1);
    size_t b = (size_t)n * HH;
    float v0 = g_agg1[b + lane] * invc + bl1[lane] + g_z1[b + lane];
    float v1 = g_agg1[b + 32 + lane] * invc + bl1[32 + lane] + g_z1[b + 32 + lane];
    float s = v0 * v0 + v1 * v1;
#pragma unroll
    for (int o = 16; o > 0; o >>= 1) s += __shfl_xor_sync(0xffffffffu, s, o);
    float inv = 1.f / fmaxf(sqrtf(s), 1e-12f);
    g_hid[b + lane]      = fmaxf(v0 * inv, 0.f);
    g_hid[b + 32 + lane] = fmaxf(v1 * inv, 0.f);
}

// ---------------- K7: fused lin1 + gemm2 -----------------------------------
// Phase A: h = relu(xa + hid @ Wlin[128:] + blin)   (h kept in SMEM per warp)
// Phase B: y2 = h @ Wl2, z2 = h @ Wr2
__global__ __launch_bounds__(256) void k_lin2(
    const float* __restrict__ Wlin, const float* __restrict__ blin,
    const float* __restrict__ Wl2, const float* __restrict__ Wr2) {
    __shared__ float sB[HH * HH];    // Wlin rows 128..191
    __shared__ float sW2[HH * 80];   // [k][0:40)=Wl2, [k][40:80)=Wr2
    __shared__ float sb[HH];
    __shared__ float sx[8 * 4 * HH]; // 8 warps * 4 rows * 64
    int tid = threadIdx.x;
    for (int i = tid; i < HH * HH; i += blockDim.x) sB[i] = Wlin[FF * HH + i];
    for (int i = tid; i < HH * CC; i += blockDim.x) {
        int k = i / CC, c = i - k * CC;
        sW2[k * 80 + c]      = Wl2[i];
        sW2[k * 80 + 40 + c] = Wr2[i];
    }
    if (tid < HH) sb[tid] = blin[tid];
    __syncthreads();
    int warp = tid >> 5, lane = tid & 31;
    int q = lane >> 3, li = lane & 7;
    float* sxw = sx + warp * (4 * HH);
    int nw = (gridDim.x * blockDim.x) >> 5;
    int gw = (blockIdx.x * blockDim.x + tid) >> 5;
    for (int grp = gw; grp < NN / 4; grp += nw) {
        int r0 = grp * 4;
        const float4* hv = reinterpret_cast<const float4*>(g_hid + (size_t)r0 * HH);
        float4* sxv = reinterpret_cast<float4*>(sxw);
        sxv[lane] = hv[lane];
        sxv[lane + 32] = hv[lane + 32];
        __syncwarp();
        // ---- Phase A: lin over K=64 ----
        u64 acc[4];
#pragma unroll
        for (int j = 0; j < 4; j++) acc[j] = 0ull;
        {
            const float* xr = sxw + q * HH;
#pragma unroll 8
            for (int k = 0; k < HH; k++) {
                float xk = xr[k];
                u64 xk2 = pack2(xk, xk);
                const ulonglong2* wp =
                    reinterpret_cast<const ulonglong2*>(sB + k * HH + li * 8);
                ulonglong2 wa = wp[0], wb = wp[1];
                ffma2(acc[0], xk2, wa.x);
                ffma2(acc[1], xk2, wa.y);
                ffma2(acc[2], xk2, wb.x);
                ffma2(acc[3], xk2, wb.y);
            }
        }
        int row = r0 + q;
        float hf[8];
        {
            const float* xap = g_xa + (size_t)row * HH + li * 8;
#pragma unroll
            for (int j = 0; j < 4; j++) {
                float2 a = unpack2(acc[j]);
                hf[2 * j]     = fmaxf(a.x + xap[2 * j]     + sb[li * 8 + 2 * j],     0.f);
                hf[2 * j + 1] = fmaxf(a.y + xap[2 * j + 1] + sb[li * 8 + 2 * j + 1], 0.f);
            }
        }
        __syncwarp();  // all lanes done reading hid from sxw
        {
            float4* hp = reinterpret_cast<float4*>(sxw + q * HH + li * 8);
            hp[0] = make_float4(hf[0], hf[1], hf[2], hf[3]);
            hp[1] = make_float4(hf[4], hf[5], hf[6], hf[7]);
        }
        __syncwarp();
        // ---- Phase B: gemm2 over K=64, 80 fused cols ----
        int c0 = li * 10;
        u64 acc2[5];
#pragma unroll
        for (int j = 0; j < 5; j++) acc2[j] = 0ull;
        {
            const float* xr = sxw + q * HH;
#pragma unroll 8
            for (int k = 0; k < HH; k++) {
                float xk = xr[k];
                u64 xk2 = pack2(xk, xk);
                const u64* wp = reinterpret_cast<const u64*>(sW2 + k * 80 + c0);
#pragma unroll
                for (int t = 0; t < 5; t++) ffma2(acc2[t], xk2, wp[t]);
            }
        }
        float* dp = (li < 4) ? (g_y2 + (size_t)row * CC + c0)
                             : (g_z2 + (size_t)row * CC + (c0 - 40));
#pragma unroll
        for (int t = 0; t < 5; t++) {
            float2 a = unpack2(acc2[t]);
            *reinterpret_cast<float2*>(dp + 2 * t) = a;
        }
        __syncwarp();
    }
}

// ---------------- K8: conv2 scatter (40 floats/edge) -----------------------
__global__ void k_scatter2() {
    unsigned idx = blockIdx.x * blockDim.x + threadIdx.x;
    if (idx >= (unsigned)EE * 10u) return;
    unsigned e = idx / 10u, c = idx - e * 10u;
    int s = g_src[e];
    int d = g_dst[e];
    float4 v = reinterpret_cast<const float4*>(g_y2 + (size_t)s * CC)[c];
    red_add_v4(g_agg2 + (size_t)d * CC + c * 4, v);
}

// ---------------- K9: out = l2norm(agg2/cnt + bl2 + z2) --------------------
__global__ void k_final(const float* __restrict__ bl2, float* __restrict__ out) {
    int gt = blockIdx.x * blockDim.x + threadIdx.x;
    int n = gt >> 5, lane = gt & 31;
    if (n >= NN) return;
    float invc = 1.f / (float)max(g_cnt[n], 1);
    size_t b = (size_t)n * CC;
    float v0 = g_agg2[b + lane] * invc + bl2[lane] + g_z2[b + lane];
    float v1 = 0.f;
    if (lane < 8)
        v1 = g_agg2[b + 32 + lane] * invc + bl2[32 + lane] + g_z2[b + 32 + lane];
    float s = v0 * v0 + v1 * v1;
#pragma unroll
    for (int o = 16; o > 0; o >>= 1) s += __shfl_xor_sync(0xffffffffu, s, o);
    float inv = 1.f / fmaxf(sqrtf(s), 1e-12f);
    out[b + lane] = v0 * inv;
    if (lane < 8) out[b + 32 + lane] = v1 * inv;
}

// ---------------------------------------------------------------------------
extern "C" void kernel_launch(void* const* d_in, const int* in_sizes, int n_in,
                              void* d_out, int out_size) {
    const float* x    = (const float*)d_in[0];
    const void*  ei   = d_in[1];               // int32 or int64, detected on-device
    const float* Wl1  = (const float*)d_in[2];
    const float* bl1  = (const float*)d_in[3];
    const float* Wr1  = (const float*)d_in[4];
    const float* Wlin = (const float*)d_in[5];
    const float* blin = (const float*)d_in[6];
    const float* Wl2  = (const float*)d_in[7];
    const float* bl2  = (const float*)d_in[8];
    const float* Wr2  = (const float*)d_in[9];
    float* out = (float*)d_out;

    // k_gemm1: weights only in SMEM = 96 KB -> 2 blocks/SM
    const int smem1 = 3 * FF * HH * (int)sizeof(float);
    cudaFuncSetAttribute(k_gemm1, cudaFuncAttributeMaxDynamicSharedMemorySize, smem1);

    k_detect<<<1, 1024>>>((const unsigned*)ei);        // launch 1
    k_zero<<<3125, 256>>>();                           // launch 2
    k_prep<<<3125, 256>>>(ei);                         // launch 3
    k_gemm1<<<296, 384, smem1>>>(x, Wl1, Wr1, Wlin);   // launch 4 <- ncu profiles this
    k_scatter1<<<50000, 256>>>();                      // E*16 work items exactly
    k_hidden<<<6250, 256>>>(bl1);                      // 50000 warps exactly
    k_lin2<<<1563, 256>>>(Wlin, blin, Wl2, Wr2);       // fused lin1 + gemm2
    k_scatter2<<<31250, 256>>>();                      // E*10 work items exactly
    k_final<<<6250, 256>>>(bl2, out);
}